// round 14
// baseline (speedup 1.0000x reference)
#include <cuda_runtime.h>
#include <cuda_fp16.h>
#include <math.h>
#include <stdint.h>

// Problem constants
#define BATCH 128
#define NOBJ  36
#define NNODE (BATCH*NOBJ)   // 4608
#define QD    2400
#define QDP   2432

typedef __half fp16;

#define SWZ128(o) ((o) ^ (((o) >> 3) & 0x70))

#define PDL_TRIGGER() asm volatile("griddepcontrol.launch_dependents;" ::: "memory")
#define PDL_WAIT()    asm volatile("griddepcontrol.wait;" ::: "memory")

__device__ __forceinline__ uint32_t smem_u32(const void* p) {
    uint32_t a;
    asm("{ .reg .u64 t; cvta.to.shared.u64 t, %1; cvt.u32.u64 %0, t; }" : "=r"(a) : "l"(p));
    return a;
}
__device__ __forceinline__ void cpa16(uint32_t s, const void* g) {
    asm volatile("cp.async.cg.shared.global [%0], [%1], 16;" :: "r"(s), "l"(g));
}
#define CP_COMMIT() asm volatile("cp.async.commit_group;" ::: "memory")
#define CP_WAIT1()  asm volatile("cp.async.wait_group 1;" ::: "memory")
#define CP_WAIT0()  asm volatile("cp.async.wait_group 0;" ::: "memory")

__device__ __forceinline__ void ldmx4(uint32_t& r0, uint32_t& r1, uint32_t& r2, uint32_t& r3, uint32_t addr) {
    asm volatile("ldmatrix.sync.aligned.m8n8.x4.shared.b16 {%0,%1,%2,%3}, [%4];"
                 : "=r"(r0), "=r"(r1), "=r"(r2), "=r"(r3) : "r"(addr));
}
__device__ __forceinline__ void mma16816(float* c, const uint32_t* a, uint32_t b0, uint32_t b1) {
    asm volatile(
        "mma.sync.aligned.m16n8k16.row.col.f32.f16.f16.f32 "
        "{%0,%1,%2,%3}, {%4,%5,%6,%7}, {%8,%9}, {%0,%1,%2,%3};"
        : "+f"(c[0]), "+f"(c[1]), "+f"(c[2]), "+f"(c[3])
        : "r"(a[0]), "r"(a[1]), "r"(a[2]), "r"(a[3]), "r"(b0), "r"(b1));
}

// ==================== scratch (no allocations allowed) ====================
__device__ __align__(128) fp16 g_qe16[128 * QDP];
__device__ __align__(128) fp16 g_ob16[NNODE * 2048];
__device__ __align__(128) fp16 g_WqT [2048 * QDP];
__device__ __align__(128) fp16 g_WvT [2048 * 2048];
__device__ __align__(128) fp16 g_W1T [1024 * 2048];
__device__ __align__(128) fp16 g_W2T [1024 * 1024];
__device__ __align__(128) fp16 g_W3T [2560 * 1024];
__device__ __align__(128) fp16 g_x16 [NNODE * 2048];
__device__ __align__(128) fp16 g_h16 [NNODE * 2560];
__device__ __align__(128) fp16 g_g116[NNODE * 1024];
__device__ __align__(128) fp16 g_g216[NNODE * 1024];

__device__ float g_q    [128 * 2048];
__device__ float g_qpart[4 * 128 * 2048];
__device__ float g_als  [NNODE * 5];
__device__ float g_ald  [NNODE * 5];
__device__ float g_als2 [NNODE * 5 * 2];
__device__ float g_ald2 [NNODE * 5 * 2];

// ==================== batched prep ====================
struct PJob { const float* src; fp16* dst; int K, N, Kp, start, tX, type; };
struct PJobs { PJob j[7]; };

__global__ __launch_bounds__(256) void prep_all(PJobs jobs)
{
    __shared__ float t[64][65];
    PDL_TRIGGER();
    int b = blockIdx.x;
    int ji = 0;
    #pragma unroll
    for (int i = 1; i < 7; i++) if (b >= jobs.j[i].start) ji = i;
    const PJob jb = jobs.j[ji];
    const int tt = b - jb.start;
    const int tid = threadIdx.x;

    if (jb.type == 0) {
        int g = tt * 256 + tid;
        int cq = jb.Kp >> 4;
        if (g >= jb.K * cq) return;
        int r = g / cq;
        int c16 = (g - r * cq) * 16;
        const float* src = jb.src + (size_t)r * jb.N + c16;
        fp16* dst = jb.dst + (size_t)r * jb.Kp + c16;
        __half2 o[8];
        #pragma unroll
        for (int j = 0; j < 4; j++) {
            float4 v = make_float4(0.f, 0.f, 0.f, 0.f);
            if (c16 + j * 4 < jb.N) v = *(const float4*)(src + j * 4);
            o[j*2+0] = __floats2half2_rn(v.x, v.y);
            o[j*2+1] = __floats2half2_rn(v.z, v.w);
        }
        *(uint4*)(dst)     = *(uint4*)&o[0];
        *(uint4*)(dst + 8) = *(uint4*)&o[4];
    } else {
        const int n0 = (tt % jb.tX) * 64;
        const int k0 = (tt / jb.tX) * 64;
        {
            int tx = tid & 15, ty = tid >> 4;
            #pragma unroll
            for (int i = 0; i < 4; i++) {
                int k = k0 + ty + i * 16;
                float4 v = make_float4(0.f, 0.f, 0.f, 0.f);
                if (k < jb.K) v = *(const float4*)(jb.src + (size_t)k * jb.N + n0 + tx * 4);
                t[ty + i * 16][tx*4+0] = v.x;
                t[ty + i * 16][tx*4+1] = v.y;
                t[ty + i * 16][tx*4+2] = v.z;
                t[ty + i * 16][tx*4+3] = v.w;
            }
        }
        __syncthreads();
        {
            int nr = tid >> 2;
            int kq = (tid & 3) * 16;
            __half2 o[8];
            #pragma unroll
            for (int j = 0; j < 8; j++)
                o[j] = __floats2half2_rn(t[kq + j*2][nr], t[kq + j*2 + 1][nr]);
            fp16* dst = jb.dst + (size_t)(n0 + nr) * jb.Kp + k0 + kq;
            *(uint4*)(dst)     = *(uint4*)&o[0];
            *(uint4*)(dst + 8) = *(uint4*)&o[4];
        }
    }
}

__global__ void combq_k(const float* __restrict__ parts, const float* __restrict__ bq, float* __restrict__ q)
{
    PDL_TRIGGER();
    PDL_WAIT();
    int idx = blockIdx.x * blockDim.x + threadIdx.x;
    if (idx >= 128 * 2048) return;
    const size_t S = (size_t)128 * 2048;
    int c = idx & 2047;
    float s = bq[c];
    #pragma unroll
    for (int p = 0; p < 4; p++) s += parts[idx + p * S];
    q[idx] = s;
}

// ==================== fp16 GEMM, KC=128 (two 64-col panels per chunk) ====================
// MR=128: 4 warps (256 th? no) — MR*2 threads; warp grid (MR/64) x 4, warp tile 64x64
#define KC 128

template<int MR>
__global__ __launch_bounds__(MR*2, 1) void gemm1(
    const fp16* __restrict__ A, const fp16* __restrict__ B,
    int N, int Kp, int kcTotal, int kcPerSplit,
    const float* __restrict__ bias, const float* __restrict__ qmul,
    float* __restrict__ Cf, fp16* __restrict__ C16,
    int mode, size_t splitStride,
    const float* __restrict__ a_s, const float* __restrict__ a_d,
    float* __restrict__ als, float* __restrict__ ald,
    int alMode, int alH, int alC, int pdl)
{
    constexpr int THREADS = MR * 2;
    constexpr uint32_t APAN = (uint32_t)MR * 128u;     // one A panel
    constexpr uint32_t ABYTES = 2u * APAN;             // A chunk (2 panels)
    constexpr uint32_t BUFSZ = ABYTES + 65536u;        // + B chunk (2x32KB)
    constexpr int MW = MR / 64;

    extern __shared__ char dsm[];
    __shared__ float s_al[2][MR];
    uint32_t sb = smem_u32(dsm);
    sb = (sb + 1023u) & ~1023u;

    PDL_TRIGGER();

    const int tid = threadIdx.x;
    const int wid = tid >> 5;
    const int L   = tid & 31;
    const int m0 = blockIdx.y * MR;
    const int n0 = blockIdx.x * 256;
    const int kc0 = blockIdx.z * kcPerSplit;
    int kc1 = kc0 + kcPerSplit; if (kc1 > kcTotal) kc1 = kcTotal;
    const int ncl = (kc1 > kc0) ? (kc1 - kc0) : 0;

    const int wm = (wid % MW) * 64;
    const int wn = (wid / MW) * 64;

    float acc[4][8][4];
    #pragma unroll
    for (int i = 0; i < 4; i++)
        #pragma unroll
        for (int j = 0; j < 8; j++)
            #pragma unroll
            for (int k = 0; k < 4; k++) acc[i][j][k] = 0.f;

    const int rA = ((L >> 3) & 1) * 8 + (L & 7);
    const int cA = (L >> 4) * 16;
    const int rB = (L >> 4) * 8 + (L & 7);
    const int cB = ((L >> 3) & 1) * 16;

    uint32_t offA[4], mskA[4];
    #pragma unroll
    for (int mf = 0; mf < 4; mf++) {
        int row = wm + mf * 16 + rA;
        offA[mf] = (uint32_t)(row * 128);
        mskA[mf] = (uint32_t)((row & 7) * 16);
    }
    uint32_t offB[4], mskB[4];
    #pragma unroll
    for (int nf2 = 0; nf2 < 4; nf2++) {
        int row = wn + nf2 * 16 + rB;
        offB[nf2] = (uint32_t)(row * 128);
        mskB[nf2] = (uint32_t)((row & 7) * 16);
    }

    // chunk layout: A panel0 | A panel1 | B panel0 (32K) | B panel1 (32K)
    auto load_A = [&](int c, int s) {
        const int k0 = c * KC;
        uint32_t base = sb + (uint32_t)s * BUFSZ;
        #pragma unroll
        for (int i = 0; i < (MR * 16) / THREADS; i++) {
            int u = tid + i * THREADS;
            int r = u >> 4, uc = u & 15;
            uint32_t so = (uint32_t)(uc >> 3) * APAN + SWZ128((uint32_t)(r * 128 + (uc & 7) * 16));
            cpa16(base + so, A + (size_t)(m0 + r) * Kp + k0 + uc * 8);
        }
    };
    auto load_B = [&](int c, int s) {
        const int k0 = c * KC;
        uint32_t base = sb + (uint32_t)s * BUFSZ + ABYTES;
        #pragma unroll
        for (int i = 0; i < 4096 / THREADS; i++) {
            int u = tid + i * THREADS;
            int r = u >> 4, uc = u & 15;
            uint32_t so = (uint32_t)(uc >> 3) * 32768u + SWZ128((uint32_t)(r * 128 + (uc & 7) * 16));
            cpa16(base + so, B + (size_t)(n0 + r) * Kp + k0 + uc * 8);
        }
    };

    if (pdl == 1) PDL_WAIT();
    if (ncl > 0) {
        if (pdl == 3) {
            load_B(kc0, 0);
            PDL_WAIT();
            load_A(kc0, 0);
        } else {
            load_A(kc0, 0);
            load_B(kc0, 0);
        }
        CP_COMMIT();
    } else if (pdl == 3) {
        PDL_WAIT();
    }

    // register-double-buffered fragments
    uint32_t afb[2][4][4], bfb[2][4][4];

    auto ldfrags = [&](uint32_t base, int ks, int buf) {
        const uint32_t pa = (uint32_t)(ks >> 2) * APAN;
        const uint32_t pb = (uint32_t)(ks >> 2) * 32768u;
        const uint32_t kb = (uint32_t)((ks & 3) * 32);
        #pragma unroll
        for (int mf = 0; mf < 4; mf++) {
            uint32_t rel = offA[mf] + ((kb + cA) ^ mskA[mf]);
            ldmx4(afb[buf][mf][0], afb[buf][mf][1], afb[buf][mf][2], afb[buf][mf][3],
                  base + pa + rel);
        }
        #pragma unroll
        for (int nf2 = 0; nf2 < 4; nf2++) {
            uint32_t rel = offB[nf2] + ((kb + cB) ^ mskB[nf2]);
            ldmx4(bfb[buf][nf2][0], bfb[buf][nf2][1], bfb[buf][nf2][2], bfb[buf][nf2][3],
                  base + ABYTES + pb + rel);
        }
    };
    auto do_mma = [&](int buf) {
        #pragma unroll
        for (int nf2 = 0; nf2 < 4; nf2++)
            #pragma unroll
            for (int mf = 0; mf < 4; mf++) {
                mma16816(acc[mf][nf2*2],   afb[buf][mf], bfb[buf][nf2][0], bfb[buf][nf2][1]);
                mma16816(acc[mf][nf2*2+1], afb[buf][mf], bfb[buf][nf2][2], bfb[buf][nf2][3]);
            }
    };

    for (int cc = 0; cc < ncl; cc++) {
        if (cc + 1 < ncl) {
            load_A(kc0 + cc + 1, (cc + 1) & 1);
            load_B(kc0 + cc + 1, (cc + 1) & 1);
            CP_COMMIT();
            CP_WAIT1();
        } else {
            CP_WAIT0();
        }
        __syncthreads();

        uint32_t base = sb + (uint32_t)(cc & 1) * BUFSZ;
        ldfrags(base, 0, 0);
        #pragma unroll
        for (int ks = 0; ks < 8; ks++) {
            if (ks < 7) ldfrags(base, ks + 1, (ks + 1) & 1);
            do_mma(ks & 1);
        }
        __syncthreads();
    }

    if (pdl == 2) PDL_WAIT();

    // ---- epilogue: store C ----
    const int rEp = (L >> 2);
    const int cEp = (L & 3) * 2;
    #pragma unroll
    for (int mf = 0; mf < 4; mf++) {
        #pragma unroll
        for (int half = 0; half < 2; half++) {
            int row = m0 + wm + mf * 16 + rEp + half * 8;
            if (mode == 0) {
                float* dst = Cf + splitStride * blockIdx.z + (size_t)row * N;
                #pragma unroll
                for (int nf = 0; nf < 8; nf++) {
                    int col = n0 + wn + nf * 8 + cEp;
                    float2 v;
                    v.x = acc[mf][nf][half*2 + 0];
                    v.y = acc[mf][nf][half*2 + 1];
                    *(float2*)(dst + col) = v;
                }
            } else if (mode == 1) {
                fp16* d16 = C16 + (size_t)row * N;
                #pragma unroll
                for (int nf = 0; nf < 8; nf++) {
                    int col = n0 + wn + nf * 8 + cEp;
                    *(__half2*)(d16 + col) =
                        __floats2half2_rn(acc[mf][nf][half*2+0], acc[mf][nf][half*2+1]);
                }
            } else {
                const float* qrow = qmul + (size_t)(row / NOBJ) * N;
                fp16* d16 = C16 + (size_t)row * N;
                #pragma unroll
                for (int nf = 0; nf < 8; nf++) {
                    int col = n0 + wn + nf * 8 + cEp;
                    float o0 = (acc[mf][nf][half*2+0] + bias[col])   * qrow[col];
                    float o1 = (acc[mf][nf][half*2+1] + bias[col+1]) * qrow[col+1];
                    *(__half2*)(d16 + col) = __floats2half2_rn(o0, o1);
                }
            }
        }
    }

    // ---- fused attention logits ----
    if (alMode) {
        if (tid < MR) { s_al[0][tid] = 0.f; s_al[1][tid] = 0.f; }
        __syncthreads();
        const int hd = n0 / alC;
        const int chBase = (n0 % alC) + wn + cEp;
        float asr[16], adr[16];
        #pragma unroll
        for (int nf = 0; nf < 8; nf++) {
            #pragma unroll
            for (int j = 0; j < 2; j++) {
                int ch = chBase + nf * 8 + j;
                asr[nf*2+j] = a_s[(size_t)hd * alC + ch];
                adr[nf*2+j] = a_d[(size_t)hd * alC + ch];
            }
        }
        #pragma unroll
        for (int mf = 0; mf < 4; mf++) {
            #pragma unroll
            for (int half = 0; half < 2; half++) {
                float ps = 0.f, pd = 0.f;
                #pragma unroll
                for (int nf = 0; nf < 8; nf++) {
                    #pragma unroll
                    for (int j = 0; j < 2; j++) {
                        float v = acc[mf][nf][half*2 + j];
                        ps = fmaf(v, asr[nf*2+j], ps);
                        pd = fmaf(v, adr[nf*2+j], pd);
                    }
                }
                ps += __shfl_xor_sync(0xffffffffu, ps, 1);
                ps += __shfl_xor_sync(0xffffffffu, ps, 2);
                pd += __shfl_xor_sync(0xffffffffu, pd, 1);
                pd += __shfl_xor_sync(0xffffffffu, pd, 2);
                if ((L & 3) == 0) {
                    int r = wm + mf * 16 + rEp + half * 8;
                    atomicAdd(&s_al[0][r], ps);
                    atomicAdd(&s_al[1][r], pd);
                }
            }
        }
        __syncthreads();
        if (tid < MR) {
            if (alMode == 1) {
                size_t oi = (size_t)(m0 + tid) * alH + hd;
                als[oi] = s_al[0][tid];
                ald[oi] = s_al[1][tid];
            } else {
                int part = (n0 % alC) >> 8;
                size_t oi = ((size_t)(m0 + tid) * alH + hd) * 2 + part;
                als[oi] = s_al[0][tid];
                ald[oi] = s_al[1][tid];
            }
        }
    }
}

// ==================== softmax helper ====================
__device__ __forceinline__ void softmax36(const float* ss, const float* sd,
                                          float (*aT)[40], int i)
{
    float di = sd[i];
    float ev[36];
    float m = -3.4e38f;
    #pragma unroll
    for (int j = 0; j < 36; j++) {
        float e = ss[j] + di;
        e = (e > 0.f) ? e : 0.2f * e;
        ev[j] = e;
        m = fmaxf(m, e);
    }
    float sum = 0.f;
    #pragma unroll
    for (int j = 0; j < 36; j++) { float x = expf(ev[j] - m); ev[j] = x; sum += x; }
    float inv = 1.0f / (sum + 1e-16f);
    #pragma unroll
    for (int j = 0; j < 36; j++) aT[j][i] = ev[j] * inv;
}

__global__ __launch_bounds__(256) void gat_agg256(
    const fp16* __restrict__ h16, const float* __restrict__ als, const float* __restrict__ ald,
    const float* __restrict__ bias, const fp16* __restrict__ resid16,
    fp16* __restrict__ out16, int H)
{
    __shared__ float sh[36][256];
    __shared__ float aT[36][40];
    __shared__ float ss[36], sd[36];

    PDL_TRIGGER();
    PDL_WAIT();

    const int bh = blockIdx.x;
    const int b = bh / H, hd = bh - b * H;
    const int tid = threadIdx.x;
    const int stride = H * 256;
    const fp16* hbase = h16 + (size_t)(b * NOBJ) * stride + hd * 256;

    for (int idx = tid; idx < 36 * 32; idx += 256) {
        int i = idx >> 5, c8 = (idx & 31) * 8;
        uint4 raw = *(const uint4*)(hbase + (size_t)i * stride + c8);
        const __half2* hp = (const __half2*)&raw;
        #pragma unroll
        for (int j = 0; j < 4; j++) {
            float2 f = __half22float2(hp[j]);
            sh[i][c8 + j*2]     = f.x;
            sh[i][c8 + j*2 + 1] = f.y;
        }
    }
    if (tid < 36) {
        ss[tid] = als[(size_t)(b * NOBJ + tid) * H + hd];
        sd[tid] = ald[(size_t)(b * NOBJ + tid) * H + hd];
    }
    __syncthreads();
    if (tid < 36) softmax36(ss, sd, aT, tid);
    __syncthreads();

    const int c = tid;
    float acc[36];
    #pragma unroll
    for (int i = 0; i < 36; i++) acc[i] = 0.f;

    #pragma unroll 4
    for (int j = 0; j < 36; j++) {
        float hv = sh[j][c];
        #pragma unroll
        for (int it = 0; it < 9; it++) {
            float4 a = *(const float4*)&aT[j][it * 4];
            acc[it*4+0] = fmaf(a.x, hv, acc[it*4+0]);
            acc[it*4+1] = fmaf(a.y, hv, acc[it*4+1]);
            acc[it*4+2] = fmaf(a.z, hv, acc[it*4+2]);
            acc[it*4+3] = fmaf(a.w, hv, acc[it*4+3]);
        }
    }

    float bv = bias[hd * 256 + c];
    #pragma unroll 4
    for (int i = 0; i < 36; i++) {
        size_t oi = (size_t)(b * NOBJ + i) * stride + hd * 256 + c;
        float o = fmaxf(acc[i] + bv, 0.f);
        if (resid16) o += __half2float(resid16[oi]);
        out16[oi] = __float2half_rn(o);
    }
}

__global__ __launch_bounds__(256) void gat_mean_k(
    const fp16* __restrict__ h16, const float* __restrict__ als2, const float* __restrict__ ald2,
    const float* __restrict__ bias, float* __restrict__ out)
{
    __shared__ float sh[36][256];
    __shared__ float aT[36][40];
    __shared__ float ss[36], sd[36];

    PDL_TRIGGER();
    PDL_WAIT();

    const int b = blockIdx.x;
    const int coff = blockIdx.y * 256;
    const int tid = threadIdx.x;

    float acc[36];
    #pragma unroll
    for (int i = 0; i < 36; i++) acc[i] = 0.f;

    for (int hd = 0; hd < 5; hd++) {
        __syncthreads();
        for (int idx = tid; idx < 36 * 32; idx += 256) {
            int i = idx >> 5, c8 = (idx & 31) * 8;
            uint4 raw = *(const uint4*)(h16 + (size_t)(b * NOBJ + i) * 2560 + hd * 512 + coff + c8);
            const __half2* hp = (const __half2*)&raw;
            #pragma unroll
            for (int j = 0; j < 4; j++) {
                float2 f = __half22float2(hp[j]);
                sh[i][c8 + j*2]     = f.x;
                sh[i][c8 + j*2 + 1] = f.y;
            }
        }
        if (tid < 36) {
            size_t base = ((size_t)(b * NOBJ + tid) * 5 + hd) * 2;
            ss[tid] = als2[base] + als2[base + 1];
            sd[tid] = ald2[base] + ald2[base + 1];
        }
        __syncthreads();
        if (tid < 36) softmax36(ss, sd, aT, tid);
        __syncthreads();

        const int c = tid;
        #pragma unroll 4
        for (int j = 0; j < 36; j++) {
            float hv = sh[j][c];
            #pragma unroll
            for (int it = 0; it < 9; it++) {
                float4 a = *(const float4*)&aT[j][it * 4];
                acc[it*4+0] = fmaf(a.x, hv, acc[it*4+0]);
                acc[it*4+1] = fmaf(a.y, hv, acc[it*4+1]);
                acc[it*4+2] = fmaf(a.z, hv, acc[it*4+2]);
                acc[it*4+3] = fmaf(a.w, hv, acc[it*4+3]);
            }
        }
    }

    float bv = bias[coff + tid];
    #pragma unroll 4
    for (int i = 0; i < 36; i++)
        out[(size_t)(b * NOBJ + i) * 512 + coff + tid] = acc[i] * 0.2f + bv;
}

// ==================== launch helpers ====================
static inline void pdl_cfg(cudaLaunchConfig_t& cfg, cudaLaunchAttribute* at,
                           dim3 grid, dim3 block, size_t smem)
{
    cfg = {};
    cfg.gridDim = grid; cfg.blockDim = block;
    cfg.dynamicSmemBytes = smem; cfg.stream = 0;
    at[0].id = cudaLaunchAttributeProgrammaticStreamSerialization;
    at[0].val.programmaticStreamSerializationAllowed = 1;
    cfg.attrs = at; cfg.numAttrs = 1;
}

// ==================== launch ====================
extern "C" void kernel_launch(void* const* d_in, const int* in_sizes, int n_in,
                              void* d_out, int out_size)
{
    const float* qe  = (const float*)d_in[0];
    const float* obj = (const float*)d_in[1];
    const float* Wq  = (const float*)d_in[3];
    const float* bq  = (const float*)d_in[4];
    const float* Wv  = (const float*)d_in[5];
    const float* bv  = (const float*)d_in[6];
    const float* W1  = (const float*)d_in[7];
    const float* a1s = (const float*)d_in[8];
    const float* a1d = (const float*)d_in[9];
    const float* b1  = (const float*)d_in[10];
    const float* W2  = (const float*)d_in[11];
    const float* a2s = (const float*)d_in[12];
    const float* a2d = (const float*)d_in[13];
    const float* b2  = (const float*)d_in[14];
    const float* W3  = (const float*)d_in[15];
    const float* a3s = (const float*)d_in[16];
    const float* a3d = (const float*)d_in[17];
    const float* b3  = (const float*)d_in[18];
    float* out = (float*)d_out;

    fp16 *qe16,*ob16,*WqT,*WvT,*W1T,*W2T,*W3T,*x16,*h16,*g116,*g216;
    float *q,*qpart,*als,*ald,*als2,*ald2;
    cudaGetSymbolAddress((void**)&qe16, g_qe16); cudaGetSymbolAddress((void**)&ob16, g_ob16);
    cudaGetSymbolAddress((void**)&WqT,  g_WqT);  cudaGetSymbolAddress((void**)&WvT,  g_WvT);
    cudaGetSymbolAddress((void**)&W1T,  g_W1T);  cudaGetSymbolAddress((void**)&W2T,  g_W2T);
    cudaGetSymbolAddress((void**)&W3T,  g_W3T);
    cudaGetSymbolAddress((void**)&x16,  g_x16);  cudaGetSymbolAddress((void**)&h16,  g_h16);
    cudaGetSymbolAddress((void**)&g116, g_g116); cudaGetSymbolAddress((void**)&g216, g_g216);
    cudaGetSymbolAddress((void**)&q,    g_q);    cudaGetSymbolAddress((void**)&qpart,g_qpart);
    cudaGetSymbolAddress((void**)&als,  g_als);  cudaGetSymbolAddress((void**)&ald,  g_ald);
    cudaGetSymbolAddress((void**)&als2, g_als2); cudaGetSymbolAddress((void**)&ald2, g_ald2);

    const int SMEM128 = 2 * (2 * 128 * 128 + 65536) + 1024;   // 197632
    const int SMEM64  = 2 * (2 * 64 * 128 + 65536) + 1024;    // 164864
    cudaFuncSetAttribute(gemm1<128>, cudaFuncAttributeMaxDynamicSharedMemorySize, SMEM128);
    cudaFuncSetAttribute(gemm1<64>,  cudaFuncAttributeMaxDynamicSharedMemorySize, SMEM64);

    // ---- batched prep (one launch) ----
    {
        PJobs jobs;
        int cursor = 0;
        auto addT = [&](int i, const float* W, fp16* WT, int K, int N, int Kp) {
            jobs.j[i] = { W, WT, K, N, Kp, cursor, N / 64, 1 };
            cursor += (N / 64) * (Kp / 64);
        };
        auto addC = [&](int i, const float* src, fp16* dst, int R, int C, int Cp) {
            int blocks = (R * (Cp / 16) + 255) / 256;
            jobs.j[i] = { src, dst, R, C, Cp, cursor, 0, 0 };
            cursor += blocks;
        };
        addT(0, Wq, WqT, QD,   2048, QDP);
        addT(1, Wv, WvT, 2048, 2048, 2048);
        addT(2, W1, W1T, 2048, 1024, 2048);
        addT(3, W2, W2T, 1024, 1024, 1024);
        addT(4, W3, W3T, 1024, 2560, 1024);
        addC(5, qe,  qe16, 128,   QD,   QDP);
        addC(6, obj, ob16, NNODE, 2048, 2048);
        prep_all<<<cursor, 256>>>(jobs);
    }

    cudaLaunchConfig_t cfg; cudaLaunchAttribute at[1];

    // q GEMM: MR=64, KC=128 -> 19 chunks, split-K 4 (kcPerSplit 5)
    gemm1<64><<<dim3(8, 2, 4), 128, SMEM64>>>(qe16, WqT, 2048, QDP, 19, 5,
                                              (const float*)nullptr, (const float*)nullptr,
                                              qpart, (fp16*)nullptr, 0, (size_t)128 * 2048,
                                              (const float*)nullptr, (const float*)nullptr,
                                              (float*)nullptr, (float*)nullptr, 0, 1, 1, 0);

    pdl_cfg(cfg, at, dim3((128 * 2048 + 255) / 256), dim3(256), 0);
    cudaLaunchKernelEx(&cfg, combq_k, (const float*)qpart, bq, q);

    // x GEMM: pdl=2
    pdl_cfg(cfg, at, dim3(8, 36, 1), dim3(256), SMEM128);
    cudaLaunchKernelEx(&cfg, gemm1<128>, (const fp16*)ob16, (const fp16*)WvT,
                       2048, 2048, 16, 16, bv, (const float*)q,
                       (float*)nullptr, x16, 2, (size_t)0,
                       (const float*)nullptr, (const float*)nullptr,
                       (float*)nullptr, (float*)nullptr, 0, 1, 1, 2);

    // layer 1: pdl=3
    pdl_cfg(cfg, at, dim3(4, 36, 1), dim3(256), SMEM128);
    cudaLaunchKernelEx(&cfg, gemm1<128>, (const fp16*)x16, (const fp16*)W1T,
                       1024, 2048, 16, 16, (const float*)nullptr, (const float*)nullptr,
                       (float*)nullptr, h16, 1, (size_t)0,
                       a1s, a1d, als, ald, 1, 4, 256, 3);
    pdl_cfg(cfg, at, dim3(BATCH * 4), dim3(256), 0);
    cudaLaunchKernelEx(&cfg, gat_agg256, (const fp16*)h16, (const float*)als, (const float*)ald,
                       b1, (const fp16*)nullptr, g116, 4);

    // layer 2: pdl=3
    pdl_cfg(cfg, at, dim3(4, 36, 1), dim3(256), SMEM128);
    cudaLaunchKernelEx(&cfg, gemm1<128>, (const fp16*)g116, (const fp16*)W2T,
                       1024, 1024, 8, 8, (const float*)nullptr, (const float*)nullptr,
                       (float*)nullptr, h16, 1, (size_t)0,
                       a2s, a2d, als, ald, 1, 4, 256, 3);
    pdl_cfg(cfg, at, dim3(BATCH * 4), dim3(256), 0);
    cudaLaunchKernelEx(&cfg, gat_agg256, (const fp16*)h16, (const float*)als, (const float*)ald,
                       b2, (const fp16*)g116, g216, 4);

    // layer 3: pdl=3, MR=64
    pdl_cfg(cfg, at, dim3(10, 72, 1), dim3(128), SMEM64);
    cudaLaunchKernelEx(&cfg, gemm1<64>, (const fp16*)g216, (const fp16*)W3T,
                       2560, 1024, 8, 8, (const float*)nullptr, (const float*)nullptr,
                       (float*)nullptr, h16, 1, (size_t)0,
                       a3s, a3d, als2, ald2, 3, 5, 512, 3);
    pdl_cfg(cfg, at, dim3(BATCH, 2), dim3(256), 0);
    cudaLaunchKernelEx(&cfg, gat_mean_k, (const fp16*)h16, (const float*)als2, (const float*)ald2,
                       b3, out);

    (void)in_sizes; (void)n_in; (void)out_size;
}

// round 15
// speedup vs baseline: 1.0334x; 1.0334x over previous
#include <cuda_runtime.h>
#include <cuda_fp16.h>
#include <math.h>
#include <stdint.h>

// Problem constants
#define BATCH 128
#define NOBJ  36
#define NNODE (BATCH*NOBJ)   // 4608
#define QD    2400
#define QDP   2432

typedef __half fp16;

#define SWZ128(o) ((o) ^ (((o) >> 3) & 0x70))

#define PDL_TRIGGER() asm volatile("griddepcontrol.launch_dependents;" ::: "memory")
#define PDL_WAIT()    asm volatile("griddepcontrol.wait;" ::: "memory")

__device__ __forceinline__ uint32_t smem_u32(const void* p) {
    uint32_t a;
    asm("{ .reg .u64 t; cvta.to.shared.u64 t, %1; cvt.u32.u64 %0, t; }" : "=r"(a) : "l"(p));
    return a;
}
__device__ __forceinline__ void cpa16(uint32_t s, const void* g) {
    asm volatile("cp.async.cg.shared.global [%0], [%1], 16;" :: "r"(s), "l"(g));
}
#define CP_COMMIT() asm volatile("cp.async.commit_group;" ::: "memory")
#define CP_WAIT1()  asm volatile("cp.async.wait_group 1;" ::: "memory")
#define CP_WAIT0()  asm volatile("cp.async.wait_group 0;" ::: "memory")

__device__ __forceinline__ void ldmx4(uint32_t& r0, uint32_t& r1, uint32_t& r2, uint32_t& r3, uint32_t addr) {
    asm volatile("ldmatrix.sync.aligned.m8n8.x4.shared.b16 {%0,%1,%2,%3}, [%4];"
                 : "=r"(r0), "=r"(r1), "=r"(r2), "=r"(r3) : "r"(addr));
}
__device__ __forceinline__ void mma16816(float* c, const uint32_t* a, uint32_t b0, uint32_t b1) {
    asm volatile(
        "mma.sync.aligned.m16n8k16.row.col.f32.f16.f16.f32 "
        "{%0,%1,%2,%3}, {%4,%5,%6,%7}, {%8,%9}, {%0,%1,%2,%3};"
        : "+f"(c[0]), "+f"(c[1]), "+f"(c[2]), "+f"(c[3])
        : "r"(a[0]), "r"(a[1]), "r"(a[2]), "r"(a[3]), "r"(b0), "r"(b1));
}

// ==================== scratch (no allocations allowed) ====================
__device__ __align__(128) fp16 g_qe16[128 * QDP];
__device__ __align__(128) fp16 g_ob16[NNODE * 2048];
__device__ __align__(128) fp16 g_WqT [2048 * QDP];
__device__ __align__(128) fp16 g_WvT [2048 * 2048];
__device__ __align__(128) fp16 g_W1T [1024 * 2048];
__device__ __align__(128) fp16 g_W2T [1024 * 1024];
__device__ __align__(128) fp16 g_W3T [2560 * 1024];
__device__ __align__(128) fp16 g_x16 [NNODE * 2048];
__device__ __align__(128) fp16 g_h16 [NNODE * 2560];
__device__ __align__(128) fp16 g_g116[NNODE * 1024];
__device__ __align__(128) fp16 g_g216[NNODE * 1024];

__device__ float g_qpart[8 * 128 * 2048];
__device__ float g_als  [NNODE * 5];
__device__ float g_ald  [NNODE * 5];
__device__ float g_als2 [NNODE * 5 * 2];
__device__ float g_ald2 [NNODE * 5 * 2];

// ==================== batched prep ====================
struct PJob { const float* src; fp16* dst; int K, N, Kp, start, tX, type; };
struct PJobs { PJob j[7]; };

__global__ __launch_bounds__(256) void prep_all(PJobs jobs)
{
    __shared__ float t[64][65];
    PDL_TRIGGER();
    int b = blockIdx.x;
    int ji = 0;
    #pragma unroll
    for (int i = 1; i < 7; i++) if (b >= jobs.j[i].start) ji = i;
    const PJob jb = jobs.j[ji];
    const int tt = b - jb.start;
    const int tid = threadIdx.x;

    if (jb.type == 0) {
        int g = tt * 256 + tid;
        int cq = jb.Kp >> 4;
        if (g >= jb.K * cq) return;
        int r = g / cq;
        int c16 = (g - r * cq) * 16;
        const float* src = jb.src + (size_t)r * jb.N + c16;
        fp16* dst = jb.dst + (size_t)r * jb.Kp + c16;
        __half2 o[8];
        #pragma unroll
        for (int j = 0; j < 4; j++) {
            float4 v = make_float4(0.f, 0.f, 0.f, 0.f);
            if (c16 + j * 4 < jb.N) v = *(const float4*)(src + j * 4);
            o[j*2+0] = __floats2half2_rn(v.x, v.y);
            o[j*2+1] = __floats2half2_rn(v.z, v.w);
        }
        *(uint4*)(dst)     = *(uint4*)&o[0];
        *(uint4*)(dst + 8) = *(uint4*)&o[4];
    } else {
        const int n0 = (tt % jb.tX) * 64;
        const int k0 = (tt / jb.tX) * 64;
        {
            int tx = tid & 15, ty = tid >> 4;
            #pragma unroll
            for (int i = 0; i < 4; i++) {
                int k = k0 + ty + i * 16;
                float4 v = make_float4(0.f, 0.f, 0.f, 0.f);
                if (k < jb.K) v = *(const float4*)(jb.src + (size_t)k * jb.N + n0 + tx * 4);
                t[ty + i * 16][tx*4+0] = v.x;
                t[ty + i * 16][tx*4+1] = v.y;
                t[ty + i * 16][tx*4+2] = v.z;
                t[ty + i * 16][tx*4+3] = v.w;
            }
        }
        __syncthreads();
        {
            int nr = tid >> 2;
            int kq = (tid & 3) * 16;
            __half2 o[8];
            #pragma unroll
            for (int j = 0; j < 8; j++)
                o[j] = __floats2half2_rn(t[kq + j*2][nr], t[kq + j*2 + 1][nr]);
            fp16* dst = jb.dst + (size_t)(n0 + nr) * jb.Kp + k0 + kq;
            *(uint4*)(dst)     = *(uint4*)&o[0];
            *(uint4*)(dst + 8) = *(uint4*)&o[4];
        }
    }
}

// ==================== fp16 GEMM, warp tile 64x64, reg-pipelined frags, KC=64 ====================
// MR=128: 8 warps (256 th), grid 2x4; MR=64: 4 warps (128 th), grid 1x4
// mode 0: Cf[splitStride*z + row*N+col] = acc
// mode 1: C16 = fp16(acc)
// mode 2: stage q from 8 split-K partials (+bq), then C16 = fp16((acc+bias)*q)
// alMode 0: none; 1: direct store; 3: half-head partial store
// pdl 0: none; 1: wait at start; 2: wait before epilogue; 3: B loads, wait, A loads
#define KC 64

template<int MR>
__global__ __launch_bounds__(MR*2, 1) void gemm1(
    const fp16* __restrict__ A, const fp16* __restrict__ B,
    int N, int Kp, int kcTotal, int kcPerSplit,
    const float* __restrict__ bias, const float* __restrict__ qparts,
    const float* __restrict__ bq,
    float* __restrict__ Cf, fp16* __restrict__ C16,
    int mode, size_t splitStride,
    const float* __restrict__ a_s, const float* __restrict__ a_d,
    float* __restrict__ als, float* __restrict__ ald,
    int alMode, int alH, int alC, int pdl)
{
    constexpr int THREADS = MR * 2;
    constexpr uint32_t ABYTES = (uint32_t)MR * 128u;
    constexpr uint32_t BUFSZ = ABYTES + 32768u;
    constexpr int MW = MR / 64;

    extern __shared__ char dsm[];
    __shared__ float s_al[2][MR];
    __shared__ float s_q[5 * 256];
    uint32_t sb = smem_u32(dsm);
    sb = (sb + 1023u) & ~1023u;

    PDL_TRIGGER();

    const int tid = threadIdx.x;
    const int wid = tid >> 5;
    const int L   = tid & 31;
    const int m0 = blockIdx.y * MR;
    const int n0 = blockIdx.x * 256;
    const int kc0 = blockIdx.z * kcPerSplit;
    int kc1 = kc0 + kcPerSplit; if (kc1 > kcTotal) kc1 = kcTotal;
    const int ncl = kc1 - kc0;

    const int wm = (wid % MW) * 64;
    const int wn = (wid / MW) * 64;

    float acc[4][8][4];
    #pragma unroll
    for (int i = 0; i < 4; i++)
        #pragma unroll
        for (int j = 0; j < 8; j++)
            #pragma unroll
            for (int k = 0; k < 4; k++) acc[i][j][k] = 0.f;

    const int rA = ((L >> 3) & 1) * 8 + (L & 7);
    const int cA = (L >> 4) * 16;
    const int rB = (L >> 4) * 8 + (L & 7);
    const int cB = ((L >> 3) & 1) * 16;

    uint32_t offA[4], mskA[4];
    #pragma unroll
    for (int mf = 0; mf < 4; mf++) {
        int row = wm + mf * 16 + rA;
        offA[mf] = (uint32_t)(row * 128);
        mskA[mf] = (uint32_t)((row & 7) * 16);
    }
    uint32_t offB[4], mskB[4];
    #pragma unroll
    for (int nf2 = 0; nf2 < 4; nf2++) {
        int row = wn + nf2 * 16 + rB;
        offB[nf2] = (uint32_t)(row * 128);
        mskB[nf2] = (uint32_t)((row & 7) * 16);
    }

    auto load_A = [&](int c, int s) {
        const int k0 = c * KC;
        uint32_t base = sb + (uint32_t)s * BUFSZ;
        #pragma unroll
        for (int i = 0; i < (MR * 8) / THREADS; i++) {
            int u = tid + i * THREADS;
            int r = u >> 3, uc = u & 7;
            uint32_t so = SWZ128((uint32_t)(r * 128 + uc * 16));
            cpa16(base + so, A + (size_t)(m0 + r) * Kp + k0 + uc * 8);
        }
    };
    auto load_B = [&](int c, int s) {
        const int k0 = c * KC;
        uint32_t base = sb + (uint32_t)s * BUFSZ;
        #pragma unroll
        for (int i = 0; i < 2048 / THREADS; i++) {
            int u = tid + i * THREADS;
            int r = u >> 3, uc = u & 7;
            uint32_t so = SWZ128((uint32_t)(r * 128 + uc * 16));
            cpa16(base + ABYTES + so, B + (size_t)(n0 + r) * Kp + k0 + uc * 8);
        }
    };

    if (pdl == 1) PDL_WAIT();
    if (pdl == 3) {
        load_B(kc0, 0);
        PDL_WAIT();
        load_A(kc0, 0);
    } else {
        load_A(kc0, 0);
        load_B(kc0, 0);
    }
    CP_COMMIT();

    uint32_t afb[2][4][4], bfb[2][4][4];

    auto ldfrags = [&](uint32_t base, int ks, int buf) {
        const uint32_t kb = (uint32_t)(ks * 32);
        #pragma unroll
        for (int mf = 0; mf < 4; mf++) {
            uint32_t rel = offA[mf] + ((kb + cA) ^ mskA[mf]);
            ldmx4(afb[buf][mf][0], afb[buf][mf][1], afb[buf][mf][2], afb[buf][mf][3], base + rel);
        }
        #pragma unroll
        for (int nf2 = 0; nf2 < 4; nf2++) {
            uint32_t rel = offB[nf2] + ((kb + cB) ^ mskB[nf2]);
            ldmx4(bfb[buf][nf2][0], bfb[buf][nf2][1], bfb[buf][nf2][2], bfb[buf][nf2][3],
                  base + ABYTES + rel);
        }
    };
    auto do_mma = [&](int buf) {
        #pragma unroll
        for (int nf2 = 0; nf2 < 4; nf2++)
            #pragma unroll
            for (int mf = 0; mf < 4; mf++) {
                mma16816(acc[mf][nf2*2],   afb[buf][mf], bfb[buf][nf2][0], bfb[buf][nf2][1]);
                mma16816(acc[mf][nf2*2+1], afb[buf][mf], bfb[buf][nf2][2], bfb[buf][nf2][3]);
            }
    };

    for (int cc = 0; cc < ncl; cc++) {
        if (cc + 1 < ncl) {
            load_A(kc0 + cc + 1, (cc + 1) & 1);
            load_B(kc0 + cc + 1, (cc + 1) & 1);
            CP_COMMIT();
            CP_WAIT1();
        } else {
            CP_WAIT0();
        }
        __syncthreads();

        uint32_t base = sb + (uint32_t)(cc & 1) * BUFSZ;
        ldfrags(base, 0, 0);
        #pragma unroll
        for (int ks = 0; ks < 4; ks++) {
            if (ks < 3) ldfrags(base, ks + 1, (ks + 1) & 1);
            do_mma(ks & 1);
        }
        __syncthreads();
    }

    if (pdl == 2) PDL_WAIT();

    // mode 2: stage q = bq + sum of 8 split-K partials for this CTA's images
    int imgBase = 0, nImg = 0;
    if (mode == 2) {
        imgBase = m0 / NOBJ;
        nImg = (m0 + MR - 1) / NOBJ - imgBase + 1;
        const size_t S = (size_t)128 * 2048;
        for (int idx = tid; idx < nImg * 256; idx += THREADS) {
            int img = imgBase + (idx >> 8);
            int c = n0 + (idx & 255);
            float s = bq[c];
            size_t off = (size_t)img * 2048 + c;
            #pragma unroll
            for (int p = 0; p < 8; p++) s += qparts[off + p * S];
            s_q[idx] = s;
        }
        __syncthreads();
    }

    // ---- epilogue: store C ----
    const int rEp = (L >> 2);
    const int cEp = (L & 3) * 2;
    #pragma unroll
    for (int mf = 0; mf < 4; mf++) {
        #pragma unroll
        for (int half = 0; half < 2; half++) {
            int row = m0 + wm + mf * 16 + rEp + half * 8;
            if (mode == 0) {
                float* dst = Cf + splitStride * blockIdx.z + (size_t)row * N;
                #pragma unroll
                for (int nf = 0; nf < 8; nf++) {
                    int col = n0 + wn + nf * 8 + cEp;
                    float2 v;
                    v.x = acc[mf][nf][half*2 + 0];
                    v.y = acc[mf][nf][half*2 + 1];
                    *(float2*)(dst + col) = v;
                }
            } else if (mode == 1) {
                fp16* d16 = C16 + (size_t)row * N;
                #pragma unroll
                for (int nf = 0; nf < 8; nf++) {
                    int col = n0 + wn + nf * 8 + cEp;
                    *(__half2*)(d16 + col) =
                        __floats2half2_rn(acc[mf][nf][half*2+0], acc[mf][nf][half*2+1]);
                }
            } else {
                const float* qrow = s_q + (row / NOBJ - imgBase) * 256 - n0;
                fp16* d16 = C16 + (size_t)row * N;
                #pragma unroll
                for (int nf = 0; nf < 8; nf++) {
                    int col = n0 + wn + nf * 8 + cEp;
                    float o0 = (acc[mf][nf][half*2+0] + bias[col])   * qrow[col];
                    float o1 = (acc[mf][nf][half*2+1] + bias[col+1]) * qrow[col+1];
                    *(__half2*)(d16 + col) = __floats2half2_rn(o0, o1);
                }
            }
        }
    }

    // ---- fused attention logits ----
    if (alMode) {
        if (tid < MR) { s_al[0][tid] = 0.f; s_al[1][tid] = 0.f; }
        __syncthreads();
        const int hd = n0 / alC;
        const int chBase = (n0 % alC) + wn + cEp;
        float asr[16], adr[16];
        #pragma unroll
        for (int nf = 0; nf < 8; nf++) {
            #pragma unroll
            for (int j = 0; j < 2; j++) {
                int ch = chBase + nf * 8 + j;
                asr[nf*2+j] = a_s[(size_t)hd * alC + ch];
                adr[nf*2+j] = a_d[(size_t)hd * alC + ch];
            }
        }
        #pragma unroll
        for (int mf = 0; mf < 4; mf++) {
            #pragma unroll
            for (int half = 0; half < 2; half++) {
                float ps = 0.f, pd = 0.f;
                #pragma unroll
                for (int nf = 0; nf < 8; nf++) {
                    #pragma unroll
                    for (int j = 0; j < 2; j++) {
                        float v = acc[mf][nf][half*2 + j];
                        ps = fmaf(v, asr[nf*2+j], ps);
                        pd = fmaf(v, adr[nf*2+j], pd);
                    }
                }
                ps += __shfl_xor_sync(0xffffffffu, ps, 1);
                ps += __shfl_xor_sync(0xffffffffu, ps, 2);
                pd += __shfl_xor_sync(0xffffffffu, pd, 1);
                pd += __shfl_xor_sync(0xffffffffu, pd, 2);
                if ((L & 3) == 0) {
                    int r = wm + mf * 16 + rEp + half * 8;
                    atomicAdd(&s_al[0][r], ps);
                    atomicAdd(&s_al[1][r], pd);
                }
            }
        }
        __syncthreads();
        if (tid < MR) {
            if (alMode == 1) {
                size_t oi = (size_t)(m0 + tid) * alH + hd;
                als[oi] = s_al[0][tid];
                ald[oi] = s_al[1][tid];
            } else {
                int part = (n0 % alC) >> 8;
                size_t oi = ((size_t)(m0 + tid) * alH + hd) * 2 + part;
                als[oi] = s_al[0][tid];
                ald[oi] = s_al[1][tid];
            }
        }
    }
}

// ==================== softmax helper ====================
__device__ __forceinline__ void softmax36(const float* ss, const float* sd,
                                          float (*aT)[40], int i)
{
    float di = sd[i];
    float ev[36];
    float m = -3.4e38f;
    #pragma unroll
    for (int j = 0; j < 36; j++) {
        float e = ss[j] + di;
        e = (e > 0.f) ? e : 0.2f * e;
        ev[j] = e;
        m = fmaxf(m, e);
    }
    float sum = 0.f;
    #pragma unroll
    for (int j = 0; j < 36; j++) { float x = expf(ev[j] - m); ev[j] = x; sum += x; }
    float inv = 1.0f / (sum + 1e-16f);
    #pragma unroll
    for (int j = 0; j < 36; j++) aT[j][i] = ev[j] * inv;
}

__global__ __launch_bounds__(256) void gat_agg256(
    const fp16* __restrict__ h16, const float* __restrict__ als, const float* __restrict__ ald,
    const float* __restrict__ bias, const fp16* __restrict__ resid16,
    fp16* __restrict__ out16, int H)
{
    __shared__ float sh[36][256];
    __shared__ float aT[36][40];
    __shared__ float ss[36], sd[36];

    PDL_TRIGGER();
    PDL_WAIT();

    const int bh = blockIdx.x;
    const int b = bh / H, hd = bh - b * H;
    const int tid = threadIdx.x;
    const int stride = H * 256;
    const fp16* hbase = h16 + (size_t)(b * NOBJ) * stride + hd * 256;

    for (int idx = tid; idx < 36 * 32; idx += 256) {
        int i = idx >> 5, c8 = (idx & 31) * 8;
        uint4 raw = *(const uint4*)(hbase + (size_t)i * stride + c8);
        const __half2* hp = (const __half2*)&raw;
        #pragma unroll
        for (int j = 0; j < 4; j++) {
            float2 f = __half22float2(hp[j]);
            sh[i][c8 + j*2]     = f.x;
            sh[i][c8 + j*2 + 1] = f.y;
        }
    }
    if (tid < 36) {
        ss[tid] = als[(size_t)(b * NOBJ + tid) * H + hd];
        sd[tid] = ald[(size_t)(b * NOBJ + tid) * H + hd];
    }
    __syncthreads();
    if (tid < 36) softmax36(ss, sd, aT, tid);
    __syncthreads();

    const int c = tid;
    float acc[36];
    #pragma unroll
    for (int i = 0; i < 36; i++) acc[i] = 0.f;

    #pragma unroll 4
    for (int j = 0; j < 36; j++) {
        float hv = sh[j][c];
        #pragma unroll
        for (int it = 0; it < 9; it++) {
            float4 a = *(const float4*)&aT[j][it * 4];
            acc[it*4+0] = fmaf(a.x, hv, acc[it*4+0]);
            acc[it*4+1] = fmaf(a.y, hv, acc[it*4+1]);
            acc[it*4+2] = fmaf(a.z, hv, acc[it*4+2]);
            acc[it*4+3] = fmaf(a.w, hv, acc[it*4+3]);
        }
    }

    float bv = bias[hd * 256 + c];
    #pragma unroll 4
    for (int i = 0; i < 36; i++) {
        size_t oi = (size_t)(b * NOBJ + i) * stride + hd * 256 + c;
        float o = fmaxf(acc[i] + bv, 0.f);
        if (resid16) o += __half2float(resid16[oi]);
        out16[oi] = __float2half_rn(o);
    }
}

__global__ __launch_bounds__(256) void gat_mean_k(
    const fp16* __restrict__ h16, const float* __restrict__ als2, const float* __restrict__ ald2,
    const float* __restrict__ bias, float* __restrict__ out)
{
    __shared__ float sh[36][256];
    __shared__ float aT[36][40];
    __shared__ float ss[36], sd[36];

    PDL_TRIGGER();
    PDL_WAIT();

    const int b = blockIdx.x;
    const int coff = blockIdx.y * 256;
    const int tid = threadIdx.x;

    float acc[36];
    #pragma unroll
    for (int i = 0; i < 36; i++) acc[i] = 0.f;

    for (int hd = 0; hd < 5; hd++) {
        __syncthreads();
        for (int idx = tid; idx < 36 * 32; idx += 256) {
            int i = idx >> 5, c8 = (idx & 31) * 8;
            uint4 raw = *(const uint4*)(h16 + (size_t)(b * NOBJ + i) * 2560 + hd * 512 + coff + c8);
            const __half2* hp = (const __half2*)&raw;
            #pragma unroll
            for (int j = 0; j < 4; j++) {
                float2 f = __half22float2(hp[j]);
                sh[i][c8 + j*2]     = f.x;
                sh[i][c8 + j*2 + 1] = f.y;
            }
        }
        if (tid < 36) {
            size_t base = ((size_t)(b * NOBJ + tid) * 5 + hd) * 2;
            ss[tid] = als2[base] + als2[base + 1];
            sd[tid] = ald2[base] + ald2[base + 1];
        }
        __syncthreads();
        if (tid < 36) softmax36(ss, sd, aT, tid);
        __syncthreads();

        const int c = tid;
        #pragma unroll 4
        for (int j = 0; j < 36; j++) {
            float hv = sh[j][c];
            #pragma unroll
            for (int it = 0; it < 9; it++) {
                float4 a = *(const float4*)&aT[j][it * 4];
                acc[it*4+0] = fmaf(a.x, hv, acc[it*4+0]);
                acc[it*4+1] = fmaf(a.y, hv, acc[it*4+1]);
                acc[it*4+2] = fmaf(a.z, hv, acc[it*4+2]);
                acc[it*4+3] = fmaf(a.w, hv, acc[it*4+3]);
            }
        }
    }

    float bv = bias[coff + tid];
    #pragma unroll 4
    for (int i = 0; i < 36; i++)
        out[(size_t)(b * NOBJ + i) * 512 + coff + tid] = acc[i] * 0.2f + bv;
}

// ==================== launch helpers ====================
static inline void pdl_cfg(cudaLaunchConfig_t& cfg, cudaLaunchAttribute* at,
                           dim3 grid, dim3 block, size_t smem)
{
    cfg = {};
    cfg.gridDim = grid; cfg.blockDim = block;
    cfg.dynamicSmemBytes = smem; cfg.stream = 0;
    at[0].id = cudaLaunchAttributeProgrammaticStreamSerialization;
    at[0].val.programmaticStreamSerializationAllowed = 1;
    cfg.attrs = at; cfg.numAttrs = 1;
}

// ==================== launch ====================
extern "C" void kernel_launch(void* const* d_in, const int* in_sizes, int n_in,
                              void* d_out, int out_size)
{
    const float* qe  = (const float*)d_in[0];
    const float* obj = (const float*)d_in[1];
    const float* Wq  = (const float*)d_in[3];
    const float* bq  = (const float*)d_in[4];
    const float* Wv  = (const float*)d_in[5];
    const float* bv  = (const float*)d_in[6];
    const float* W1  = (const float*)d_in[7];
    const float* a1s = (const float*)d_in[8];
    const float* a1d = (const float*)d_in[9];
    const float* b1  = (const float*)d_in[10];
    const float* W2  = (const float*)d_in[11];
    const float* a2s = (const float*)d_in[12];
    const float* a2d = (const float*)d_in[13];
    const float* b2  = (const float*)d_in[14];
    const float* W3  = (const float*)d_in[15];
    const float* a3s = (const float*)d_in[16];
    const float* a3d = (const float*)d_in[17];
    const float* b3  = (const float*)d_in[18];
    float* out = (float*)d_out;

    fp16 *qe16,*ob16,*WqT,*WvT,*W1T,*W2T,*W3T,*x16,*h16,*g116,*g216;
    float *qpart,*als,*ald,*als2,*ald2;
    cudaGetSymbolAddress((void**)&qe16, g_qe16); cudaGetSymbolAddress((void**)&ob16, g_ob16);
    cudaGetSymbolAddress((void**)&WqT,  g_WqT);  cudaGetSymbolAddress((void**)&WvT,  g_WvT);
    cudaGetSymbolAddress((void**)&W1T,  g_W1T);  cudaGetSymbolAddress((void**)&W2T,  g_W2T);
    cudaGetSymbolAddress((void**)&W3T,  g_W3T);
    cudaGetSymbolAddress((void**)&x16,  g_x16);  cudaGetSymbolAddress((void**)&h16,  g_h16);
    cudaGetSymbolAddress((void**)&g116, g_g116); cudaGetSymbolAddress((void**)&g216, g_g216);
    cudaGetSymbolAddress((void**)&qpart,g_qpart);
    cudaGetSymbolAddress((void**)&als,  g_als);  cudaGetSymbolAddress((void**)&ald,  g_ald);
    cudaGetSymbolAddress((void**)&als2, g_als2); cudaGetSymbolAddress((void**)&ald2, g_ald2);

    const int SMEM128 = 2 * (128 * 128 + 32768) + 1024;   // 99328
    const int SMEM64  = 2 * (64 * 128 + 32768) + 1024;    // 82944
    cudaFuncSetAttribute(gemm1<128>, cudaFuncAttributeMaxDynamicSharedMemorySize, SMEM128);
    cudaFuncSetAttribute(gemm1<64>,  cudaFuncAttributeMaxDynamicSharedMemorySize, SMEM64);

    // ---- batched prep (one launch) ----
    {
        PJobs jobs;
        int cursor = 0;
        auto addT = [&](int i, const float* W, fp16* WT, int K, int N, int Kp) {
            jobs.j[i] = { W, WT, K, N, Kp, cursor, N / 64, 1 };
            cursor += (N / 64) * (Kp / 64);
        };
        auto addC = [&](int i, const float* src, fp16* dst, int R, int C, int Cp) {
            int blocks = (R * (Cp / 16) + 255) / 256;
            jobs.j[i] = { src, dst, R, C, Cp, cursor, 0, 0 };
            cursor += blocks;
        };
        addT(0, Wq, WqT, QD,   2048, QDP);
        addT(1, Wv, WvT, 2048, 2048, 2048);
        addT(2, W1, W1T, 2048, 1024, 2048);
        addT(3, W2, W2T, 1024, 1024, 1024);
        addT(4, W3, W3T, 1024, 2560, 1024);
        addC(5, qe,  qe16, 128,   QD,   QDP);
        addC(6, obj, ob16, NNODE, 2048, 2048);
        prep_all<<<cursor, 256>>>(jobs);
    }

    cudaLaunchConfig_t cfg; cudaLaunchAttribute at[1];

    // q GEMM (MR=64, 128 threads), split-K 8, KC=64 -> 38 chunks
    gemm1<64><<<dim3(8, 2, 8), 128, SMEM64>>>(qe16, WqT, 2048, QDP, 38, 5,
                                              (const float*)nullptr, (const float*)nullptr,
                                              (const float*)nullptr,
                                              qpart, (fp16*)nullptr, 0, (size_t)128 * 2048,
                                              (const float*)nullptr, (const float*)nullptr,
                                              (float*)nullptr, (float*)nullptr, 0, 1, 1, 0);

    // x GEMM: pdl=2 (mainloop free; waits for q partials before staging q in epilogue)
    pdl_cfg(cfg, at, dim3(8, 36, 1), dim3(256), SMEM128);
    cudaLaunchKernelEx(&cfg, gemm1<128>, (const fp16*)ob16, (const fp16*)WvT,
                       2048, 2048, 32, 32, bv, (const float*)qpart, bq,
                       (float*)nullptr, x16, 2, (size_t)0,
                       (const float*)nullptr, (const float*)nullptr,
                       (float*)nullptr, (float*)nullptr, 0, 1, 1, 2);

    // layer 1: pdl=3
    pdl_cfg(cfg, at, dim3(4, 36, 1), dim3(256), SMEM128);
    cudaLaunchKernelEx(&cfg, gemm1<128>, (const fp16*)x16, (const fp16*)W1T,
                       1024, 2048, 32, 32, (const float*)nullptr, (const float*)nullptr,
                       (const float*)nullptr,
                       (float*)nullptr, h16, 1, (size_t)0,
                       a1s, a1d, als, ald, 1, 4, 256, 3);
    pdl_cfg(cfg, at, dim3(BATCH * 4), dim3(256), 0);
    cudaLaunchKernelEx(&cfg, gat_agg256, (const fp16*)h16, (const float*)als, (const float*)ald,
                       b1, (const fp16*)nullptr, g116, 4);

    // layer 2: pdl=3
    pdl_cfg(cfg, at, dim3(4, 36, 1), dim3(256), SMEM128);
    cudaLaunchKernelEx(&cfg, gemm1<128>, (const fp16*)g116, (const fp16*)W2T,
                       1024, 1024, 16, 16, (const float*)nullptr, (const float*)nullptr,
                       (const float*)nullptr,
                       (float*)nullptr, h16, 1, (size_t)0,
                       a2s, a2d, als, ald, 1, 4, 256, 3);
    pdl_cfg(cfg, at, dim3(BATCH * 4), dim3(256), 0);
    cudaLaunchKernelEx(&cfg, gat_agg256, (const fp16*)h16, (const float*)als, (const float*)ald,
                       b2, (const fp16*)g116, g216, 4);

    // layer 3: pdl=3, MR=64
    pdl_cfg(cfg, at, dim3(10, 72, 1), dim3(128), SMEM64);
    cudaLaunchKernelEx(&cfg, gemm1<64>, (const fp16*)g216, (const fp16*)W3T,
                       2560, 1024, 16, 16, (const float*)nullptr, (const float*)nullptr,
                       (const float*)nullptr,
                       (float*)nullptr, h16, 1, (size_t)0,
                       a3s, a3d, als2, ald2, 3, 5, 512, 3);
    pdl_cfg(cfg, at, dim3(BATCH, 2), dim3(256), 0);
    cudaLaunchKernelEx(&cfg, gat_mean_k, (const fp16*)h16, (const float*)als2, (const float*)ald2,
                       b3, out);

    (void)in_sizes; (void)n_in; (void)out_size;
}

// round 16
// speedup vs baseline: 1.0834x; 1.0484x over previous
#include <cuda_runtime.h>
#include <cuda_fp16.h>
#include <math.h>
#include <stdint.h>

// Problem constants
#define BATCH 128
#define NOBJ  36
#define NNODE (BATCH*NOBJ)   // 4608
#define QD    2400
#define QDP   2432

typedef __half fp16;

#define SWZ128(o) ((o) ^ (((o) >> 3) & 0x70))

#define PDL_TRIGGER() asm volatile("griddepcontrol.launch_dependents;" ::: "memory")
#define PDL_WAIT()    asm volatile("griddepcontrol.wait;" ::: "memory")

__device__ __forceinline__ uint32_t smem_u32(const void* p) {
    uint32_t a;
    asm("{ .reg .u64 t; cvta.to.shared.u64 t, %1; cvt.u32.u64 %0, t; }" : "=r"(a) : "l"(p));
    return a;
}
__device__ __forceinline__ void cpa16(uint32_t s, const void* g) {
    asm volatile("cp.async.cg.shared.global [%0], [%1], 16;" :: "r"(s), "l"(g));
}
#define CP_COMMIT() asm volatile("cp.async.commit_group;" ::: "memory")
#define CP_WAIT1()  asm volatile("cp.async.wait_group 1;" ::: "memory")
#define CP_WAIT0()  asm volatile("cp.async.wait_group 0;" ::: "memory")

__device__ __forceinline__ void ldmx4(uint32_t& r0, uint32_t& r1, uint32_t& r2, uint32_t& r3, uint32_t addr) {
    asm volatile("ldmatrix.sync.aligned.m8n8.x4.shared.b16 {%0,%1,%2,%3}, [%4];"
                 : "=r"(r0), "=r"(r1), "=r"(r2), "=r"(r3) : "r"(addr));
}
__device__ __forceinline__ void mma16816(float* c, const uint32_t* a, uint32_t b0, uint32_t b1) {
    asm volatile(
        "mma.sync.aligned.m16n8k16.row.col.f32.f16.f16.f32 "
        "{%0,%1,%2,%3}, {%4,%5,%6,%7}, {%8,%9}, {%0,%1,%2,%3};"
        : "+f"(c[0]), "+f"(c[1]), "+f"(c[2]), "+f"(c[3])
        : "r"(a[0]), "r"(a[1]), "r"(a[2]), "r"(a[3]), "r"(b0), "r"(b1));
}

// ==================== scratch (no allocations allowed) ====================
__device__ __align__(128) fp16 g_qe16[128 * QDP];
__device__ __align__(128) fp16 g_ob16[NNODE * 2048];
__device__ __align__(128) fp16 g_WqT [2048 * QDP];
__device__ __align__(128) fp16 g_WvT [2048 * 2048];
__device__ __align__(128) fp16 g_W1T [1024 * 2048];
__device__ __align__(128) fp16 g_W2T [1024 * 1024];
__device__ __align__(128) fp16 g_W3T [2560 * 1024];
__device__ __align__(128) fp16 g_x16 [NNODE * 2048];
__device__ __align__(128) fp16 g_h16 [NNODE * 2560];
__device__ __align__(128) fp16 g_g116[NNODE * 1024];
__device__ __align__(128) fp16 g_g216[NNODE * 1024];

__device__ float g_q    [128 * 2048];
__device__ float g_qpart[8 * 128 * 2048];
__device__ float g_alsP [NNODE * 5 * 4];   // partial logits, up to 4 parts per head
__device__ float g_aldP [NNODE * 5 * 4];

// ==================== batched prep ====================
struct PJob { const float* src; fp16* dst; int K, N, Kp, start, tX, type; };
struct PJobs { PJob j[7]; };

__global__ __launch_bounds__(256) void prep_all(PJobs jobs)
{
    __shared__ float t[64][65];
    PDL_TRIGGER();
    int b = blockIdx.x;
    int ji = 0;
    #pragma unroll
    for (int i = 1; i < 7; i++) if (b >= jobs.j[i].start) ji = i;
    const PJob jb = jobs.j[ji];
    const int tt = b - jb.start;
    const int tid = threadIdx.x;

    if (jb.type == 0) {
        int g = tt * 256 + tid;
        int cq = jb.Kp >> 4;
        if (g >= jb.K * cq) return;
        int r = g / cq;
        int c16 = (g - r * cq) * 16;
        const float* src = jb.src + (size_t)r * jb.N + c16;
        fp16* dst = jb.dst + (size_t)r * jb.Kp + c16;
        __half2 o[8];
        #pragma unroll
        for (int j = 0; j < 4; j++) {
            float4 v = make_float4(0.f, 0.f, 0.f, 0.f);
            if (c16 + j * 4 < jb.N) v = *(const float4*)(src + j * 4);
            o[j*2+0] = __floats2half2_rn(v.x, v.y);
            o[j*2+1] = __floats2half2_rn(v.z, v.w);
        }
        *(uint4*)(dst)     = *(uint4*)&o[0];
        *(uint4*)(dst + 8) = *(uint4*)&o[4];
    } else {
        const int n0 = (tt % jb.tX) * 64;
        const int k0 = (tt / jb.tX) * 64;
        {
            int tx = tid & 15, ty = tid >> 4;
            #pragma unroll
            for (int i = 0; i < 4; i++) {
                int k = k0 + ty + i * 16;
                float4 v = make_float4(0.f, 0.f, 0.f, 0.f);
                if (k < jb.K) v = *(const float4*)(jb.src + (size_t)k * jb.N + n0 + tx * 4);
                t[ty + i * 16][tx*4+0] = v.x;
                t[ty + i * 16][tx*4+1] = v.y;
                t[ty + i * 16][tx*4+2] = v.z;
                t[ty + i * 16][tx*4+3] = v.w;
            }
        }
        __syncthreads();
        {
            int nr = tid >> 2;
            int kq = (tid & 3) * 16;
            __half2 o[8];
            #pragma unroll
            for (int j = 0; j < 8; j++)
                o[j] = __floats2half2_rn(t[kq + j*2][nr], t[kq + j*2 + 1][nr]);
            fp16* dst = jb.dst + (size_t)(n0 + nr) * jb.Kp + k0 + kq;
            *(uint4*)(dst)     = *(uint4*)&o[0];
            *(uint4*)(dst + 8) = *(uint4*)&o[4];
        }
    }
}

__global__ void combq_k(const float* __restrict__ parts, const float* __restrict__ bq, float* __restrict__ q)
{
    PDL_TRIGGER();
    PDL_WAIT();
    int idx = blockIdx.x * blockDim.x + threadIdx.x;
    if (idx >= 128 * 2048) return;
    const size_t S = (size_t)128 * 2048;
    int c = idx & 2047;
    float s = bq[c];
    #pragma unroll
    for (int p = 0; p < 8; p++) s += parts[idx + p * S];
    q[idx] = s;
}

// ==================== fp16 GEMM: CTA tile 128x128, 4 warps (2x2), 2 CTAs/SM ====================
// mode 0: Cf[splitStride*z + row*N+col] = acc
// mode 1: C16 = fp16(acc)
// mode 2: C16 = fp16((acc + bias[col]) * qmul[(row/36)*N+col])
// alMode 0: none; 1: partial store, part index (n0%alC)/128, nParts=alC/128
// pdl 0: none; 1: wait at start; 2: wait before epilogue; 3: B loads, wait, A loads
#define KC 64
#define MR 128
#define NRT 128
#define THREADS 128
#define ABYTES 16384u
#define BUFSZ  32768u
#define GEMM_SMEM (2*BUFSZ + 1024)

__global__ __launch_bounds__(THREADS, 2) void gemm1(
    const fp16* __restrict__ A, const fp16* __restrict__ B,
    int N, int Kp, int kcTotal, int kcPerSplit,
    const float* __restrict__ bias, const float* __restrict__ qmul,
    float* __restrict__ Cf, fp16* __restrict__ C16,
    int mode, size_t splitStride,
    const float* __restrict__ a_s, const float* __restrict__ a_d,
    float* __restrict__ als, float* __restrict__ ald,
    int alMode, int alH, int alC, int pdl)
{
    extern __shared__ char dsm[];
    __shared__ float s_al[2][MR];
    uint32_t sb = smem_u32(dsm);
    sb = (sb + 1023u) & ~1023u;

    PDL_TRIGGER();

    const int tid = threadIdx.x;
    const int wid = tid >> 5;
    const int L   = tid & 31;
    const int m0 = blockIdx.y * MR;
    const int n0 = blockIdx.x * NRT;
    const int kc0 = blockIdx.z * kcPerSplit;
    int kc1 = kc0 + kcPerSplit; if (kc1 > kcTotal) kc1 = kcTotal;
    const int ncl = kc1 - kc0;

    const int wm = (wid & 1) * 64;
    const int wn = (wid >> 1) * 64;

    float acc[4][8][4];
    #pragma unroll
    for (int i = 0; i < 4; i++)
        #pragma unroll
        for (int j = 0; j < 8; j++)
            #pragma unroll
            for (int k = 0; k < 4; k++) acc[i][j][k] = 0.f;

    const int rA = ((L >> 3) & 1) * 8 + (L & 7);
    const int cA = (L >> 4) * 16;
    const int rB = (L >> 4) * 8 + (L & 7);
    const int cB = ((L >> 3) & 1) * 16;

    uint32_t offA[4], mskA[4];
    #pragma unroll
    for (int mf = 0; mf < 4; mf++) {
        int row = wm + mf * 16 + rA;
        offA[mf] = (uint32_t)(row * 128);
        mskA[mf] = (uint32_t)((row & 7) * 16);
    }
    uint32_t offB[4], mskB[4];
    #pragma unroll
    for (int nf2 = 0; nf2 < 4; nf2++) {
        int row = wn + nf2 * 16 + rB;
        offB[nf2] = (uint32_t)(row * 128);
        mskB[nf2] = (uint32_t)((row & 7) * 16);
    }

    auto load_A = [&](int c, int s) {
        const int k0 = c * KC;
        uint32_t base = sb + (uint32_t)s * BUFSZ;
        #pragma unroll
        for (int i = 0; i < 8; i++) {
            int u = tid + i * THREADS;
            int r = u >> 3, uc = u & 7;
            uint32_t so = SWZ128((uint32_t)(r * 128 + uc * 16));
            cpa16(base + so, A + (size_t)(m0 + r) * Kp + k0 + uc * 8);
        }
    };
    auto load_B = [&](int c, int s) {
        const int k0 = c * KC;
        uint32_t base = sb + (uint32_t)s * BUFSZ;
        #pragma unroll
        for (int i = 0; i < 8; i++) {
            int u = tid + i * THREADS;
            int r = u >> 3, uc = u & 7;
            uint32_t so = SWZ128((uint32_t)(r * 128 + uc * 16));
            cpa16(base + ABYTES + so, B + (size_t)(n0 + r) * Kp + k0 + uc * 8);
        }
    };

    if (pdl == 1) PDL_WAIT();
    if (pdl == 3) {
        load_B(kc0, 0);
        PDL_WAIT();
        load_A(kc0, 0);
    } else {
        load_A(kc0, 0);
        load_B(kc0, 0);
    }
    CP_COMMIT();

    uint32_t afb[2][4][4], bfb[2][4][4];

    auto ldfrags = [&](uint32_t base, int ks, int buf) {
        const uint32_t kb = (uint32_t)(ks * 32);
        #pragma unroll
        for (int mf = 0; mf < 4; mf++) {
            uint32_t rel = offA[mf] + ((kb + cA) ^ mskA[mf]);
            ldmx4(afb[buf][mf][0], afb[buf][mf][1], afb[buf][mf][2], afb[buf][mf][3], base + rel);
        }
        #pragma unroll
        for (int nf2 = 0; nf2 < 4; nf2++) {
            uint32_t rel = offB[nf2] + ((kb + cB) ^ mskB[nf2]);
            ldmx4(bfb[buf][nf2][0], bfb[buf][nf2][1], bfb[buf][nf2][2], bfb[buf][nf2][3],
                  base + ABYTES + rel);
        }
    };
    auto do_mma = [&](int buf) {
        #pragma unroll
        for (int nf2 = 0; nf2 < 4; nf2++)
            #pragma unroll
            for (int mf = 0; mf < 4; mf++) {
                mma16816(acc[mf][nf2*2],   afb[buf][mf], bfb[buf][nf2][0], bfb[buf][nf2][1]);
                mma16816(acc[mf][nf2*2+1], afb[buf][mf], bfb[buf][nf2][2], bfb[buf][nf2][3]);
            }
    };

    for (int cc = 0; cc < ncl; cc++) {
        if (cc + 1 < ncl) {
            load_A(kc0 + cc + 1, (cc + 1) & 1);
            load_B(kc0 + cc + 1, (cc + 1) & 1);
            CP_COMMIT();
            CP_WAIT1();
        } else {
            CP_WAIT0();
        }
        __syncthreads();

        uint32_t base = sb + (uint32_t)(cc & 1) * BUFSZ;
        ldfrags(base, 0, 0);
        #pragma unroll
        for (int ks = 0; ks < 4; ks++) {
            if (ks < 3) ldfrags(base, ks + 1, (ks + 1) & 1);
            do_mma(ks & 1);
        }
        __syncthreads();
    }

    if (pdl == 2) PDL_WAIT();

    // ---- epilogue: store C ----
    const int rEp = (L >> 2);
    const int cEp = (L & 3) * 2;
    #pragma unroll
    for (int mf = 0; mf < 4; mf++) {
        #pragma unroll
        for (int half = 0; half < 2; half++) {
            int row = m0 + wm + mf * 16 + rEp + half * 8;
            if (mode == 0) {
                float* dst = Cf + splitStride * blockIdx.z + (size_t)row * N;
                #pragma unroll
                for (int nf = 0; nf < 8; nf++) {
                    int col = n0 + wn + nf * 8 + cEp;
                    float2 v;
                    v.x = acc[mf][nf][half*2 + 0];
                    v.y = acc[mf][nf][half*2 + 1];
                    *(float2*)(dst + col) = v;
                }
            } else if (mode == 1) {
                fp16* d16 = C16 + (size_t)row * N;
                #pragma unroll
                for (int nf = 0; nf < 8; nf++) {
                    int col = n0 + wn + nf * 8 + cEp;
                    *(__half2*)(d16 + col) =
                        __floats2half2_rn(acc[mf][nf][half*2+0], acc[mf][nf][half*2+1]);
                }
            } else {
                const float* qrow = qmul + (size_t)(row / NOBJ) * N;
                fp16* d16 = C16 + (size_t)row * N;
                #pragma unroll
                for (int nf = 0; nf < 8; nf++) {
                    int col = n0 + wn + nf * 8 + cEp;
                    float o0 = (acc[mf][nf][half*2+0] + bias[col])   * qrow[col];
                    float o1 = (acc[mf][nf][half*2+1] + bias[col+1]) * qrow[col+1];
                    *(__half2*)(d16 + col) = __floats2half2_rn(o0, o1);
                }
            }
        }
    }

    // ---- fused attention logits: partial store, part = (n0%alC)/128 ----
    if (alMode) {
        if (tid < MR) { s_al[0][tid] = 0.f; s_al[1][tid] = 0.f; }
        __syncthreads();
        const int hd = n0 / alC;
        const int nParts = alC >> 7;
        const int part = (n0 % alC) >> 7;
        const int chBase = (n0 % alC) + wn + cEp;
        float asr[16], adr[16];
        #pragma unroll
        for (int nf = 0; nf < 8; nf++) {
            #pragma unroll
            for (int j = 0; j < 2; j++) {
                int ch = chBase + nf * 8 + j;
                asr[nf*2+j] = a_s[(size_t)hd * alC + ch];
                adr[nf*2+j] = a_d[(size_t)hd * alC + ch];
            }
        }
        #pragma unroll
        for (int mf = 0; mf < 4; mf++) {
            #pragma unroll
            for (int half = 0; half < 2; half++) {
                float ps = 0.f, pd = 0.f;
                #pragma unroll
                for (int nf = 0; nf < 8; nf++) {
                    #pragma unroll
                    for (int j = 0; j < 2; j++) {
                        float v = acc[mf][nf][half*2 + j];
                        ps = fmaf(v, asr[nf*2+j], ps);
                        pd = fmaf(v, adr[nf*2+j], pd);
                    }
                }
                ps += __shfl_xor_sync(0xffffffffu, ps, 1);
                ps += __shfl_xor_sync(0xffffffffu, ps, 2);
                pd += __shfl_xor_sync(0xffffffffu, pd, 1);
                pd += __shfl_xor_sync(0xffffffffu, pd, 2);
                if ((L & 3) == 0) {
                    int r = wm + mf * 16 + rEp + half * 8;
                    atomicAdd(&s_al[0][r], ps);
                    atomicAdd(&s_al[1][r], pd);
                }
            }
        }
        __syncthreads();
        if (tid < MR) {
            size_t oi = ((size_t)(m0 + tid) * alH + hd) * (size_t)nParts + part;
            als[oi] = s_al[0][tid];
            ald[oi] = s_al[1][tid];
        }
    }
}

// ==================== softmax helper ====================
__device__ __forceinline__ void softmax36(const float* ss, const float* sd,
                                          float (*aT)[40], int i)
{
    float di = sd[i];
    float ev[36];
    float m = -3.4e38f;
    #pragma unroll
    for (int j = 0; j < 36; j++) {
        float e = ss[j] + di;
        e = (e > 0.f) ? e : 0.2f * e;
        ev[j] = e;
        m = fmaxf(m, e);
    }
    float sum = 0.f;
    #pragma unroll
    for (int j = 0; j < 36; j++) { float x = expf(ev[j] - m); ev[j] = x; sum += x; }
    float inv = 1.0f / (sum + 1e-16f);
    #pragma unroll
    for (int j = 0; j < 36; j++) aT[j][i] = ev[j] * inv;
}

// GAT aggregation C=256 concat + relu (+fp16 residual); logits from 2 partials
__global__ __launch_bounds__(256) void gat_agg256(
    const fp16* __restrict__ h16, const float* __restrict__ alsP, const float* __restrict__ aldP,
    const float* __restrict__ bias, const fp16* __restrict__ resid16,
    fp16* __restrict__ out16, int H)
{
    __shared__ float sh[36][256];
    __shared__ float aT[36][40];
    __shared__ float ss[36], sd[36];

    PDL_TRIGGER();
    PDL_WAIT();

    const int bh = blockIdx.x;
    const int b = bh / H, hd = bh - b * H;
    const int tid = threadIdx.x;
    const int stride = H * 256;
    const fp16* hbase = h16 + (size_t)(b * NOBJ) * stride + hd * 256;

    for (int idx = tid; idx < 36 * 32; idx += 256) {
        int i = idx >> 5, c8 = (idx & 31) * 8;
        uint4 raw = *(const uint4*)(hbase + (size_t)i * stride + c8);
        const __half2* hp = (const __half2*)&raw;
        #pragma unroll
        for (int j = 0; j < 4; j++) {
            float2 f = __half22float2(hp[j]);
            sh[i][c8 + j*2]     = f.x;
            sh[i][c8 + j*2 + 1] = f.y;
        }
    }
    if (tid < 36) {
        size_t base = ((size_t)(b * NOBJ + tid) * H + hd) * 2;
        ss[tid] = alsP[base] + alsP[base + 1];
        sd[tid] = aldP[base] + aldP[base + 1];
    }
    __syncthreads();
    if (tid < 36) softmax36(ss, sd, aT, tid);
    __syncthreads();

    const int c = tid;
    float acc[36];
    #pragma unroll
    for (int i = 0; i < 36; i++) acc[i] = 0.f;

    #pragma unroll 4
    for (int j = 0; j < 36; j++) {
        float hv = sh[j][c];
        #pragma unroll
        for (int it = 0; it < 9; it++) {
            float4 a = *(const float4*)&aT[j][it * 4];
            acc[it*4+0] = fmaf(a.x, hv, acc[it*4+0]);
            acc[it*4+1] = fmaf(a.y, hv, acc[it*4+1]);
            acc[it*4+2] = fmaf(a.z, hv, acc[it*4+2]);
            acc[it*4+3] = fmaf(a.w, hv, acc[it*4+3]);
        }
    }

    float bv = bias[hd * 256 + c];
    #pragma unroll 4
    for (int i = 0; i < 36; i++) {
        size_t oi = (size_t)(b * NOBJ + i) * stride + hd * 256 + c;
        float o = fmaxf(acc[i] + bv, 0.f);
        if (resid16) o += __half2float(resid16[oi]);
        out16[oi] = __float2half_rn(o);
    }
}

// GAT layer 3: C=512, H=5, mean over heads + b3; logits from 4 partials
__global__ __launch_bounds__(256) void gat_mean_k(
    const fp16* __restrict__ h16, const float* __restrict__ alsP, const float* __restrict__ aldP,
    const float* __restrict__ bias, float* __restrict__ out)
{
    __shared__ float sh[36][256];
    __shared__ float aT[36][40];
    __shared__ float ss[36], sd[36];

    PDL_TRIGGER();
    PDL_WAIT();

    const int b = blockIdx.x;
    const int coff = blockIdx.y * 256;
    const int tid = threadIdx.x;

    float acc[36];
    #pragma unroll
    for (int i = 0; i < 36; i++) acc[i] = 0.f;

    for (int hd = 0; hd < 5; hd++) {
        __syncthreads();
        for (int idx = tid; idx < 36 * 32; idx += 256) {
            int i = idx >> 5, c8 = (idx & 31) * 8;
            uint4 raw = *(const uint4*)(h16 + (size_t)(b * NOBJ + i) * 2560 + hd * 512 + coff + c8);
            const __half2* hp = (const __half2*)&raw;
            #pragma unroll
            for (int j = 0; j < 4; j++) {
                float2 f = __half22float2(hp[j]);
                sh[i][c8 + j*2]     = f.x;
                sh[i][c8 + j*2 + 1] = f.y;
            }
        }
        if (tid < 36) {
            size_t base = ((size_t)(b * NOBJ + tid) * 5 + hd) * 4;
            ss[tid] = (alsP[base] + alsP[base + 1]) + (alsP[base + 2] + alsP[base + 3]);
            sd[tid] = (aldP[base] + aldP[base + 1]) + (aldP[base + 2] + aldP[base + 3]);
        }
        __syncthreads();
        if (tid < 36) softmax36(ss, sd, aT, tid);
        __syncthreads();

        const int c = tid;
        #pragma unroll 4
        for (int j = 0; j < 36; j++) {
            float hv = sh[j][c];
            #pragma unroll
            for (int it = 0; it < 9; it++) {
                float4 a = *(const float4*)&aT[j][it * 4];
                acc[it*4+0] = fmaf(a.x, hv, acc[it*4+0]);
                acc[it*4+1] = fmaf(a.y, hv, acc[it*4+1]);
                acc[it*4+2] = fmaf(a.z, hv, acc[it*4+2]);
                acc[it*4+3] = fmaf(a.w, hv, acc[it*4+3]);
            }
        }
    }

    float bv = bias[coff + tid];
    #pragma unroll 4
    for (int i = 0; i < 36; i++)
        out[(size_t)(b * NOBJ + i) * 512 + coff + tid] = acc[i] * 0.2f + bv;
}

// ==================== launch helpers ====================
static inline void pdl_cfg(cudaLaunchConfig_t& cfg, cudaLaunchAttribute* at,
                           dim3 grid, dim3 block, size_t smem)
{
    cfg = {};
    cfg.gridDim = grid; cfg.blockDim = block;
    cfg.dynamicSmemBytes = smem; cfg.stream = 0;
    at[0].id = cudaLaunchAttributeProgrammaticStreamSerialization;
    at[0].val.programmaticStreamSerializationAllowed = 1;
    cfg.attrs = at; cfg.numAttrs = 1;
}

// ==================== launch ====================
extern "C" void kernel_launch(void* const* d_in, const int* in_sizes, int n_in,
                              void* d_out, int out_size)
{
    const float* qe  = (const float*)d_in[0];
    const float* obj = (const float*)d_in[1];
    const float* Wq  = (const float*)d_in[3];
    const float* bq  = (const float*)d_in[4];
    const float* Wv  = (const float*)d_in[5];
    const float* bv  = (const float*)d_in[6];
    const float* W1  = (const float*)d_in[7];
    const float* a1s = (const float*)d_in[8];
    const float* a1d = (const float*)d_in[9];
    const float* b1  = (const float*)d_in[10];
    const float* W2  = (const float*)d_in[11];
    const float* a2s = (const float*)d_in[12];
    const float* a2d = (const float*)d_in[13];
    const float* b2  = (const float*)d_in[14];
    const float* W3  = (const float*)d_in[15];
    const float* a3s = (const float*)d_in[16];
    const float* a3d = (const float*)d_in[17];
    const float* b3  = (const float*)d_in[18];
    float* out = (float*)d_out;

    fp16 *qe16,*ob16,*WqT,*WvT,*W1T,*W2T,*W3T,*x16,*h16,*g116,*g216;
    float *q,*qpart,*alsP,*aldP;
    cudaGetSymbolAddress((void**)&qe16, g_qe16); cudaGetSymbolAddress((void**)&ob16, g_ob16);
    cudaGetSymbolAddress((void**)&WqT,  g_WqT);  cudaGetSymbolAddress((void**)&WvT,  g_WvT);
    cudaGetSymbolAddress((void**)&W1T,  g_W1T);  cudaGetSymbolAddress((void**)&W2T,  g_W2T);
    cudaGetSymbolAddress((void**)&W3T,  g_W3T);
    cudaGetSymbolAddress((void**)&x16,  g_x16);  cudaGetSymbolAddress((void**)&h16,  g_h16);
    cudaGetSymbolAddress((void**)&g116, g_g116); cudaGetSymbolAddress((void**)&g216, g_g216);
    cudaGetSymbolAddress((void**)&q,    g_q);    cudaGetSymbolAddress((void**)&qpart,g_qpart);
    cudaGetSymbolAddress((void**)&alsP, g_alsP); cudaGetSymbolAddress((void**)&aldP, g_aldP);

    cudaFuncSetAttribute(gemm1, cudaFuncAttributeMaxDynamicSharedMemorySize, GEMM_SMEM);

    // ---- batched prep (one launch) ----
    {
        PJobs jobs;
        int cursor = 0;
        auto addT = [&](int i, const float* W, fp16* WT, int K, int N, int Kp) {
            jobs.j[i] = { W, WT, K, N, Kp, cursor, N / 64, 1 };
            cursor += (N / 64) * (Kp / 64);
        };
        auto addC = [&](int i, const float* src, fp16* dst, int R, int C, int Cp) {
            int blocks = (R * (Cp / 16) + 255) / 256;
            jobs.j[i] = { src, dst, R, C, Cp, cursor, 0, 0 };
            cursor += blocks;
        };
        addT(0, Wq, WqT, QD,   2048, QDP);
        addT(1, Wv, WvT, 2048, 2048, 2048);
        addT(2, W1, W1T, 2048, 1024, 2048);
        addT(3, W2, W2T, 1024, 1024, 1024);
        addT(4, W3, W3T, 1024, 2560, 1024);
        addC(5, qe,  qe16, 128,   QD,   QDP);
        addC(6, obj, ob16, NNODE, 2048, 2048);
        prep_all<<<cursor, 256>>>(jobs);
    }

    cudaLaunchConfig_t cfg; cudaLaunchAttribute at[1];

    // q GEMM: N-tiles of 128 -> 16, split-K 8 -> 128 CTAs (plain launch: waits for prep)
    gemm1<<<dim3(16, 1, 8), THREADS, GEMM_SMEM>>>(qe16, WqT, 2048, QDP, 38, 5,
                                                  (const float*)nullptr, (const float*)nullptr,
                                                  qpart, (fp16*)nullptr, 0, (size_t)128 * 2048,
                                                  (const float*)nullptr, (const float*)nullptr,
                                                  (float*)nullptr, (float*)nullptr, 0, 1, 1, 0);

    pdl_cfg(cfg, at, dim3((128 * 2048 + 255) / 256), dim3(256), 0);
    cudaLaunchKernelEx(&cfg, combq_k, (const float*)qpart, bq, q);

    // x GEMM: 16 x 36 = 576 CTAs; pdl=2 (mainloop free; epilogue waits for q)
    pdl_cfg(cfg, at, dim3(16, 36, 1), dim3(THREADS), GEMM_SMEM);
    cudaLaunchKernelEx(&cfg, gemm1, (const fp16*)ob16, (const fp16*)WvT,
                       2048, 2048, 32, 32, bv, (const float*)q,
                       (float*)nullptr, x16, 2, (size_t)0,
                       (const float*)nullptr, (const float*)nullptr,
                       (float*)nullptr, (float*)nullptr, 0, 1, 1, 2);

    // layer 1: 8 x 36 = 288 CTAs; pdl=3; logits 2 partials/head
    pdl_cfg(cfg, at, dim3(8, 36, 1), dim3(THREADS), GEMM_SMEM);
    cudaLaunchKernelEx(&cfg, gemm1, (const fp16*)x16, (const fp16*)W1T,
                       1024, 2048, 32, 32, (const float*)nullptr, (const float*)nullptr,
                       (float*)nullptr, h16, 1, (size_t)0,
                       a1s, a1d, alsP, aldP, 1, 4, 256, 3);
    pdl_cfg(cfg, at, dim3(BATCH * 4), dim3(256), 0);
    cudaLaunchKernelEx(&cfg, gat_agg256, (const fp16*)h16, (const float*)alsP, (const float*)aldP,
                       b1, (const fp16*)nullptr, g116, 4);

    // layer 2: pdl=3
    pdl_cfg(cfg, at, dim3(8, 36, 1), dim3(THREADS), GEMM_SMEM);
    cudaLaunchKernelEx(&cfg, gemm1, (const fp16*)g116, (const fp16*)W2T,
                       1024, 1024, 16, 16, (const float*)nullptr, (const float*)nullptr,
                       (float*)nullptr, h16, 1, (size_t)0,
                       a2s, a2d, alsP, aldP, 1, 4, 256, 3);
    pdl_cfg(cfg, at, dim3(BATCH * 4), dim3(256), 0);
    cudaLaunchKernelEx(&cfg, gat_agg256, (const fp16*)h16, (const float*)alsP, (const float*)aldP,
                       b2, (const fp16*)g116, g216, 4);

    // layer 3: 20 x 36 = 720 CTAs; pdl=3; logits 4 partials/head
    pdl_cfg(cfg, at, dim3(20, 36, 1), dim3(THREADS), GEMM_SMEM);
    cudaLaunchKernelEx(&cfg, gemm1, (const fp16*)g216, (const fp16*)W3T,
                       2560, 1024, 16, 16, (const float*)nullptr, (const float*)nullptr,
                       (float*)nullptr, h16, 1, (size_t)0,
                       a3s, a3d, alsP, aldP, 1, 5, 512, 3);
    pdl_cfg(cfg, at, dim3(BATCH, 2), dim3(256), 0);
    cudaLaunchKernelEx(&cfg, gat_mean_k, (const fp16*)h16, (const float*)alsP, (const float*)aldP,
                       b3, out);

    (void)in_sizes; (void)n_in; (void)out_size;
}